// round 14
// baseline (speedup 1.0000x reference)
#include <cuda_runtime.h>

#define NC 22
#define NP 1024
#define BMAX 256
#define QS 4              // q-segments per batch
#define SEGQ (NP / QS)    // q's per segment = 256
#define PCH 2             // p-chunks per batch (512 p each)
#define BLKB (QS * PCH)   // kernel B blocks per symmetric batch = 8
#define TPB_B 128
#define PT 4              // points per thread: PCH*TPB_B*PT == NP
#define TPB_A 128
#define MARGIN 0.01f
#define FINF_BITS 0x7F800000

__device__ float4     g_G[BMAX][NP];       // (-2gx, -2gy, -2gz, |g|^2)
__device__ float4     g_xp[BMAX][NP];      // (ax, ay, az, |a|^2)
__device__ int        g_pmin[BMAX * NP];   // clamped min dist as ordered int bits
__device__ int        g_sym_cnt;           // reset by last block each launch
__device__ int        g_sym_list[BMAX];
__device__ float      g_partial[BMAX];     // asym per-batch partials (scaled)
__device__ unsigned   g_done;              // self-resetting via atomicInc wrap

__device__ __forceinline__ void quat2rot(float w, float x, float y, float z, float* R) {
    R[0] = 1.f - 2.f * (y * y + z * z);
    R[1] = 2.f * (x * y - z * w);
    R[2] = 2.f * (x * z + y * w);
    R[3] = 2.f * (x * y + z * w);
    R[4] = 1.f - 2.f * (x * x + z * z);
    R[5] = 2.f * (y * z - x * w);
    R[6] = 2.f * (x * z - y * w);
    R[7] = 2.f * (y * z + x * w);
    R[8] = 1.f - 2.f * (x * x + y * y);
}

// ---------------- Kernel A: prep + asymmetric diag path ----------------
__global__ __launch_bounds__(TPB_A) void adl_prep_kernel(
    const float* __restrict__ poses_pred,
    const float* __restrict__ poses_target,
    const float* __restrict__ poses_weight,
    const float* __restrict__ points,
    const float* __restrict__ symmetry,
    float inv_scale)
{
    __shared__ float s_red[TPB_A / 32];
    const int b   = blockIdx.x;
    const int tid = threadIdx.x;

    // class selection: first i with weight[b, 4i] > 0
    int  cls   = 0;
    bool valid = false;
    #pragma unroll
    for (int i = 0; i < NC; i++) {
        float w = poses_weight[b * 4 * NC + 4 * i];
        if (!valid && w > 0.f) { cls = i; valid = true; }
    }
    if (!valid) {
        if (tid == 0) g_partial[b] = 0.f;
        return;
    }

    const float* qp = poses_pred   + b * 4 * NC + 4 * cls;
    const float* qg = poses_target + b * 4 * NC + 4 * cls;
    float Rp[9], Rg[9];
    quat2rot(qp[0], qp[1], qp[2], qp[3], Rp);
    quat2rot(qg[0], qg[1], qg[2], qg[3], Rg);
    const bool   sym = symmetry[cls] > 0.f;
    const float* pts = points + (size_t)cls * NP * 3;

    float acc = 0.f;
    for (int j = tid; j < NP; j += TPB_A) {
        const float* p0 = pts + (size_t)j * 3;
        float x0 = p0[0], y0 = p0[1], z0 = p0[2];

        float gx = Rg[0] * x0 + Rg[1] * y0 + Rg[2] * z0;
        float gy = Rg[3] * x0 + Rg[4] * y0 + Rg[5] * z0;
        float gz = Rg[6] * x0 + Rg[7] * y0 + Rg[8] * z0;

        float ax = Rp[0] * x0 + Rp[1] * y0 + Rp[2] * z0;
        float ay = Rp[3] * x0 + Rp[4] * y0 + Rp[5] * z0;
        float az = Rp[6] * x0 + Rp[7] * y0 + Rp[8] * z0;

        if (sym) {
            float n  = gx * gx + gy * gy + gz * gz;
            float na = ax * ax + ay * ay + az * az;
            g_G[b][j]  = make_float4(-2.f * gx, -2.f * gy, -2.f * gz, n);
            g_xp[b][j] = make_float4(ax, ay, az, na);
            g_pmin[b * NP + j] = FINF_BITS;
        } else {
            float dx = ax - gx, dy = ay - gy, dz = az - gz;
            float d = dx * dx + dy * dy + dz * dz;
            acc += 0.5f * fmaxf(d - MARGIN, 0.f);
        }
    }

    if (sym) {
        if (tid == 0) g_partial[b] = 0.f;
        __syncthreads();   // all tile/pmin writes done before publish
        if (tid == 0) {
            __threadfence();
            int idx = atomicAdd(&g_sym_cnt, 1);
            g_sym_list[idx] = b;
        }
        return;
    }

    // block reduce asym contribution -> own slot
    acc *= inv_scale;
    #pragma unroll
    for (int off = 16; off > 0; off >>= 1)
        acc += __shfl_down_sync(0xFFFFFFFFu, acc, off);
    if ((tid & 31) == 0) s_red[tid >> 5] = acc;
    __syncthreads();
    if (tid == 0) {
        float v = 0.f;
        #pragma unroll
        for (int k = 0; k < TPB_A / 32; k++) v += s_red[k];
        g_partial[b] = v;
    }
}

// ------- Kernel B: q-split symmetric ADD-S (scalar FFMA) + final reduce -------
__global__ __launch_bounds__(TPB_B) void adl_sym_kernel(
    float* __restrict__ out, int out_size, float inv_scale, int B)
{
    __shared__ float4 s_G[SEGQ];
    __shared__ float  s_red[TPB_B / 32];

    const int i     = blockIdx.x;
    const int tid   = threadIdx.x;
    const int total = B * BLKB;
    const int cnt   = g_sym_cnt;

    if (i < cnt * BLKB) {
        const int b      = g_sym_list[i / BLKB];
        const int sub    = i % BLKB;
        const int pchunk = sub & (PCH - 1);
        const int qseg   = sub / PCH;

        // stage this q-segment into shared (SEGQ == 2*TPB_B)
        s_G[tid]         = g_G[b][qseg * SEGQ + tid];
        s_G[tid + TPB_B] = g_G[b][qseg * SEGQ + tid + TPB_B];
        __syncthreads();

        const int p_base = pchunk * (TPB_B * PT) + tid;
        float ax[PT], ay[PT], az[PT], nn[PT];
        #pragma unroll
        for (int u = 0; u < PT; u++) {
            float4 x = g_xp[b][p_base + u * TPB_B];
            ax[u] = x.x; ay[u] = x.y; az[u] = x.z; nn[u] = x.w;
        }

        float mA[PT], mB[PT];
        #pragma unroll
        for (int u = 0; u < PT; u++) { mA[u] = 3.4e38f; mB[u] = 3.4e38f; }

        #pragma unroll 2
        for (int j = 0; j < SEGQ; j += 2) {
            float4 G0 = s_G[j + 0];   // broadcast LDS.128
            float4 G1 = s_G[j + 1];
            #pragma unroll
            for (int u = 0; u < PT; u++) {
                float d0 = fmaf(ax[u], G0.x, fmaf(ay[u], G0.y, fmaf(az[u], G0.z, G0.w)));
                float d1 = fmaf(ax[u], G1.x, fmaf(ay[u], G1.y, fmaf(az[u], G1.z, G1.w)));
                mA[u] = fminf(mA[u], d0);
                mB[u] = fminf(mB[u], d1);
            }
        }

        #pragma unroll
        for (int u = 0; u < PT; u++) {
            // max(.,0) commutes with min (monotone); clamp now so bits order as ints
            float d = fmaxf(fminf(mA[u], mB[u]) + nn[u], 0.f);
            atomicMin(&g_pmin[b * NP + p_base + u * TPB_B], __float_as_int(d));
        }
    }

    // ---- last-block final reduction (self-resetting counter) ----
    __shared__ unsigned s_last;
    __threadfence();
    if (tid == 0)
        s_last = (atomicInc(&g_done, (unsigned)total - 1) == (unsigned)total - 1);
    __syncthreads();
    if (s_last) {
        float vs = 0.f;
        for (int s = 0; s < cnt; s++) {
            const int b = g_sym_list[s];
            for (int k = tid; k < NP; k += TPB_B) {
                float d = __int_as_float(g_pmin[b * NP + k]);
                vs += fmaxf(d - MARGIN, 0.f);
            }
        }
        float v = vs * (0.5f * inv_scale);
        for (int k = tid; k < B; k += TPB_B) v += g_partial[k];
        #pragma unroll
        for (int off = 16; off > 0; off >>= 1)
            v += __shfl_down_sync(0xFFFFFFFFu, v, off);
        if ((tid & 31) == 0) s_red[tid >> 5] = v;
        __syncthreads();
        if (tid == 0) {
            out[0] = s_red[0] + s_red[1] + s_red[2] + s_red[3];
            for (int k = 1; k < out_size; k++) out[k] = 0.f;
            g_sym_cnt = 0;   // reset for next launch / graph replay
        }
    }
}

extern "C" void kernel_launch(void* const* d_in, const int* in_sizes, int n_in,
                              void* d_out, int out_size) {
    const float* poses_pred   = (const float*)d_in[0];
    const float* poses_target = (const float*)d_in[1];
    const float* poses_weight = (const float*)d_in[2];
    const float* points       = (const float*)d_in[3];
    const float* symmetry     = (const float*)d_in[4];
    float* out = (float*)d_out;

    const int B = in_sizes[0] / (4 * NC);
    const float inv_scale = 1.0f / ((float)B * (float)NP);

    adl_prep_kernel<<<B, TPB_A>>>(
        poses_pred, poses_target, poses_weight, points, symmetry, inv_scale);

    adl_sym_kernel<<<B * BLKB, TPB_B>>>(out, out_size, inv_scale, B);
}

// round 15
// speedup vs baseline: 2.1234x; 2.1234x over previous
#include <cuda_runtime.h>

#define NC 22
#define NP 1024
#define BMAX 256
#define QS 8              // q-segments per batch
#define SEG (NP / 2 / QS) // q-PAIRS per segment = 64
#define PCH 2             // p-chunks per batch (512 p each)
#define BLKB (QS * PCH)   // kernel B blocks per symmetric batch = 16
#define TPB_B 128
#define PT 4              // points per thread: PCH*TPB_B*PT == NP
#define TPB_A 128
#define MARGIN 0.01f
#define FINF_BITS 0x7F800000

typedef unsigned long long ull;

__device__ ulonglong2 g_A[BMAX][NP / 2];   // ((-2gx_e,-2gx_o),(-2gy_e,-2gy_o))
__device__ ulonglong2 g_Bt[BMAX][NP / 2];  // ((-2gz_e,-2gz_o),(|g_e|^2,|g_o|^2))
__device__ float4     g_xp[BMAX][NP];      // (ax, ay, az, |a|^2)
__device__ int        g_pmin[BMAX * NP];   // clamped min dist as ordered int bits
__device__ int        g_sym_cnt;           // reset by global-last block each launch
__device__ int        g_sym_list[BMAX];
__device__ float      g_partial[BMAX];     // asym per-batch partials (scaled)
__device__ float      g_bsum[BMAX];        // sym per-batch hinge sums (scaled)
__device__ unsigned   g_bdone[BMAX];       // per-batch counters (self-reset via wrap)
__device__ unsigned   g_done;              // global counter (self-reset via wrap)

__device__ __forceinline__ ull fma2(ull a, ull b, ull c) {
    ull d;
    asm("fma.rn.f32x2 %0, %1, %2, %3;" : "=l"(d) : "l"(a), "l"(b), "l"(c));
    return d;
}
__device__ __forceinline__ ull pack2(float lo, float hi) {
    ull d;
    asm("mov.b64 %0, {%1, %2};" : "=l"(d) : "f"(lo), "f"(hi));
    return d;
}
__device__ __forceinline__ void unpack2(ull v, float& lo, float& hi) {
    asm("mov.b64 {%0, %1}, %2;" : "=f"(lo), "=f"(hi) : "l"(v));
}

__device__ __forceinline__ void quat2rot(float w, float x, float y, float z, float* R) {
    R[0] = 1.f - 2.f * (y * y + z * z);
    R[1] = 2.f * (x * y - z * w);
    R[2] = 2.f * (x * z + y * w);
    R[3] = 2.f * (x * y + z * w);
    R[4] = 1.f - 2.f * (x * x + z * z);
    R[5] = 2.f * (y * z - x * w);
    R[6] = 2.f * (x * z - y * w);
    R[7] = 2.f * (y * z + x * w);
    R[8] = 1.f - 2.f * (x * x + y * y);
}

// ---------------- Kernel A: prep + asymmetric diag path ----------------
__global__ __launch_bounds__(TPB_A) void adl_prep_kernel(
    const float* __restrict__ poses_pred,
    const float* __restrict__ poses_target,
    const float* __restrict__ poses_weight,
    const float* __restrict__ points,
    const float* __restrict__ symmetry,
    float inv_scale)
{
    __shared__ float s_red[TPB_A / 32];
    const int b   = blockIdx.x;
    const int tid = threadIdx.x;

    int  cls   = 0;
    bool valid = false;
    #pragma unroll
    for (int i = 0; i < NC; i++) {
        float w = poses_weight[b * 4 * NC + 4 * i];
        if (!valid && w > 0.f) { cls = i; valid = true; }
    }
    if (!valid) {
        if (tid == 0) g_partial[b] = 0.f;
        return;
    }

    const float* qp = poses_pred   + b * 4 * NC + 4 * cls;
    const float* qg = poses_target + b * 4 * NC + 4 * cls;
    float Rp[9], Rg[9];
    quat2rot(qp[0], qp[1], qp[2], qp[3], Rp);
    quat2rot(qg[0], qg[1], qg[2], qg[3], Rg);
    const bool   sym = symmetry[cls] > 0.f;
    const float* pts = points + (size_t)cls * NP * 3;

    float acc = 0.f;
    #pragma unroll
    for (int j = tid; j < NP / 2; j += TPB_A) {
        const float* p0 = pts + (size_t)(2 * j) * 3;
        float x0 = p0[0], y0 = p0[1], z0 = p0[2];
        float x1 = p0[3], y1 = p0[4], z1 = p0[5];

        float gx0 = Rg[0] * x0 + Rg[1] * y0 + Rg[2] * z0;
        float gy0 = Rg[3] * x0 + Rg[4] * y0 + Rg[5] * z0;
        float gz0 = Rg[6] * x0 + Rg[7] * y0 + Rg[8] * z0;
        float gx1 = Rg[0] * x1 + Rg[1] * y1 + Rg[2] * z1;
        float gy1 = Rg[3] * x1 + Rg[4] * y1 + Rg[5] * z1;
        float gz1 = Rg[6] * x1 + Rg[7] * y1 + Rg[8] * z1;

        float ax0 = Rp[0] * x0 + Rp[1] * y0 + Rp[2] * z0;
        float ay0 = Rp[3] * x0 + Rp[4] * y0 + Rp[5] * z0;
        float az0 = Rp[6] * x0 + Rp[7] * y0 + Rp[8] * z0;
        float ax1 = Rp[0] * x1 + Rp[1] * y1 + Rp[2] * z1;
        float ay1 = Rp[3] * x1 + Rp[4] * y1 + Rp[5] * z1;
        float az1 = Rp[6] * x1 + Rp[7] * y1 + Rp[8] * z1;

        if (sym) {
            float n0 = gx0 * gx0 + gy0 * gy0 + gz0 * gz0;
            float n1 = gx1 * gx1 + gy1 * gy1 + gz1 * gz1;
            ulonglong2 A, B;
            A.x = pack2(-2.f * gx0, -2.f * gx1);
            A.y = pack2(-2.f * gy0, -2.f * gy1);
            B.x = pack2(-2.f * gz0, -2.f * gz1);
            B.y = pack2(n0, n1);
            g_A[b][j]  = A;
            g_Bt[b][j] = B;
            g_xp[b][2 * j + 0] = make_float4(ax0, ay0, az0, ax0 * ax0 + ay0 * ay0 + az0 * az0);
            g_xp[b][2 * j + 1] = make_float4(ax1, ay1, az1, ax1 * ax1 + ay1 * ay1 + az1 * az1);
            g_pmin[b * NP + 2 * j + 0] = FINF_BITS;
            g_pmin[b * NP + 2 * j + 1] = FINF_BITS;
        } else {
            float dx0 = ax0 - gx0, dy0 = ay0 - gy0, dz0 = az0 - gz0;
            float dx1 = ax1 - gx1, dy1 = ay1 - gy1, dz1 = az1 - gz1;
            float d0 = dx0 * dx0 + dy0 * dy0 + dz0 * dz0;
            float d1 = dx1 * dx1 + dy1 * dy1 + dz1 * dz1;
            acc += 0.5f * fmaxf(d0 - MARGIN, 0.f) + 0.5f * fmaxf(d1 - MARGIN, 0.f);
        }
    }

    if (sym) {
        if (tid == 0) {
            g_partial[b] = 0.f;
            int idx = atomicAdd(&g_sym_cnt, 1);
            g_sym_list[idx] = b;
        }
        return;
    }

    acc *= inv_scale;
    #pragma unroll
    for (int off = 16; off > 0; off >>= 1)
        acc += __shfl_down_sync(0xFFFFFFFFu, acc, off);
    if ((tid & 31) == 0) s_red[tid >> 5] = acc;
    __syncthreads();
    if (tid == 0) {
        float v = 0.f;
        #pragma unroll
        for (int k = 0; k < TPB_A / 32; k++) v += s_red[k];
        g_partial[b] = v;
    }
}

// ------- Kernel B: q-split ADD-S + per-batch finish + global finish -------
__global__ __launch_bounds__(TPB_B) void adl_sym_kernel(
    float* __restrict__ out, int out_size, float inv_scale, int B)
{
    __shared__ ulonglong2 s_A[SEG];
    __shared__ ulonglong2 s_B[SEG];
    __shared__ float s_red[TPB_B / 32];
    __shared__ unsigned s_flag;

    const int i     = blockIdx.x;
    const int tid   = threadIdx.x;
    const int total = B * BLKB;
    const int cnt   = g_sym_cnt;

    if (i < cnt * BLKB) {
        const int b      = g_sym_list[i / BLKB];
        const int sub    = i % BLKB;
        const int pchunk = sub & (PCH - 1);
        const int qseg   = sub / PCH;

        // stage q-segment (SEG=64 ulonglong2 pairs)
        if (tid < SEG) {
            s_A[tid] = g_A[b][qseg * SEG + tid];
            s_B[tid] = g_Bt[b][qseg * SEG + tid];
        }
        __syncthreads();

        const int p_base = pchunk * (TPB_B * PT) + tid;
        float4 xp[PT];
        ull ax[PT], ay[PT], az[PT];
        #pragma unroll
        for (int u = 0; u < PT; u++) {
            xp[u] = g_xp[b][p_base + u * TPB_B];
            ax[u] = pack2(xp[u].x, xp[u].x);
            ay[u] = pack2(xp[u].y, xp[u].y);
            az[u] = pack2(xp[u].z, xp[u].z);
        }

        float mA[PT], mB[PT];
        #pragma unroll
        for (int u = 0; u < PT; u++) { mA[u] = 3.4e38f; mB[u] = 3.4e38f; }

        #pragma unroll 2
        for (int j = 0; j < SEG; j += 2) {
            ulonglong2 A0 = s_A[j + 0], B0 = s_B[j + 0];
            ulonglong2 A1 = s_A[j + 1], B1 = s_B[j + 1];
            #pragma unroll
            for (int u = 0; u < PT; u++) {
                ull t0 = fma2(ax[u], A0.x, fma2(ay[u], A0.y, fma2(az[u], B0.x, B0.y)));
                ull t1 = fma2(ax[u], A1.x, fma2(ay[u], A1.y, fma2(az[u], B1.x, B1.y)));
                float l0, h0, l1, h1;
                unpack2(t0, l0, h0);
                unpack2(t1, l1, h1);
                mA[u] = fminf(mA[u], fminf(l0, h0));
                mB[u] = fminf(mB[u], fminf(l1, h1));
            }
        }

        #pragma unroll
        for (int u = 0; u < PT; u++) {
            // max(.,0) commutes with min (monotone); clamp so bits order as ints
            float d = fmaxf(fminf(mA[u], mB[u]) + xp[u].w, 0.f);
            atomicMin(&g_pmin[b * NP + p_base + u * TPB_B], __float_as_int(d));
        }

        // ---- per-batch finish: 16th block of this batch reduces its pmins ----
        __syncthreads();
        if (tid == 0) {
            __threadfence();
            s_flag = (atomicInc(&g_bdone[b], (unsigned)BLKB - 1) == (unsigned)BLKB - 1);
        }
        __syncthreads();
        if (s_flag) {
            float vs = 0.f;
            #pragma unroll
            for (int k = tid; k < NP; k += TPB_B) {
                float d = __int_as_float(__ldcg(&g_pmin[b * NP + k]));
                vs += fmaxf(d - MARGIN, 0.f);
            }
            vs *= 0.5f * inv_scale;
            #pragma unroll
            for (int off = 16; off > 0; off >>= 1)
                vs += __shfl_down_sync(0xFFFFFFFFu, vs, off);
            if ((tid & 31) == 0) s_red[tid >> 5] = vs;
            __syncthreads();
            if (tid == 0) g_bsum[b] = s_red[0] + s_red[1] + s_red[2] + s_red[3];
        }
    }

    // ---- global finish (self-resetting counter) ----
    if (tid == 0) {
        __threadfence();
        s_flag = (atomicInc(&g_done, (unsigned)total - 1) == (unsigned)total - 1);
    }
    __syncthreads();
    if (s_flag) {
        float v = 0.f;
        for (int s = tid; s < cnt; s += TPB_B)
            v += __ldcg(&g_bsum[g_sym_list[s]]);
        for (int k = tid; k < B; k += TPB_B)
            v += __ldcg(&g_partial[k]);
        #pragma unroll
        for (int off = 16; off > 0; off >>= 1)
            v += __shfl_down_sync(0xFFFFFFFFu, v, off);
        if ((tid & 31) == 0) s_red[tid >> 5] = v;
        __syncthreads();
        if (tid == 0) {
            out[0] = s_red[0] + s_red[1] + s_red[2] + s_red[3];
            for (int k = 1; k < out_size; k++) out[k] = 0.f;
            g_sym_cnt = 0;   // reset for next launch / graph replay
        }
    }
}

extern "C" void kernel_launch(void* const* d_in, const int* in_sizes, int n_in,
                              void* d_out, int out_size) {
    const float* poses_pred   = (const float*)d_in[0];
    const float* poses_target = (const float*)d_in[1];
    const float* poses_weight = (const float*)d_in[2];
    const float* points       = (const float*)d_in[3];
    const float* symmetry     = (const float*)d_in[4];
    float* out = (float*)d_out;

    const int B = in_sizes[0] / (4 * NC);
    const float inv_scale = 1.0f / ((float)B * (float)NP);

    adl_prep_kernel<<<B, TPB_A>>>(
        poses_pred, poses_target, poses_weight, points, symmetry, inv_scale);

    adl_sym_kernel<<<B * BLKB, TPB_B>>>(out, out_size, inv_scale, B);
}

// round 16
// speedup vs baseline: 2.2449x; 1.0572x over previous
#include <cuda_runtime.h>

#define NC 22
#define NP 1024
#define BMAX 256
#define QS 8              // q-segments per batch
#define SEG (NP / 2 / QS) // q-PAIRS per segment = 64
#define PCH 2             // p-chunks per batch (512 p each)
#define BLKB (QS * PCH)   // blocks per batch = 16
#define TPB 128
#define PT 4              // points per thread: PCH*TPB*PT == NP
#define MARGIN 0.01f
#define FINF_BITS 0x7F800000

typedef unsigned long long ull;

__device__ int        g_pmin[BMAX * NP];   // keys: FINF_BITS - bits(d); 0 = empty (static zero-init, reset by finisher)
__device__ float      g_bsum[BMAX];        // per-batch sums (scaled)
__device__ unsigned   g_bdone[BMAX];       // per-batch counters (self-reset via wrap)
__device__ unsigned   g_done;              // global counter (self-reset via wrap)

__device__ __forceinline__ ull fma2(ull a, ull b, ull c) {
    ull d;
    asm("fma.rn.f32x2 %0, %1, %2, %3;" : "=l"(d) : "l"(a), "l"(b), "l"(c));
    return d;
}
__device__ __forceinline__ ull pack2(float lo, float hi) {
    ull d;
    asm("mov.b64 %0, {%1, %2};" : "=l"(d) : "f"(lo), "f"(hi));
    return d;
}
__device__ __forceinline__ void unpack2(ull v, float& lo, float& hi) {
    asm("mov.b64 {%0, %1}, %2;" : "=f"(lo), "=f"(hi) : "l"(v));
}

__device__ __forceinline__ void quat2rot(float w, float x, float y, float z, float* R) {
    R[0] = 1.f - 2.f * (y * y + z * z);
    R[1] = 2.f * (x * y - z * w);
    R[2] = 2.f * (x * z + y * w);
    R[3] = 2.f * (x * y + z * w);
    R[4] = 1.f - 2.f * (x * x + z * z);
    R[5] = 2.f * (y * z - x * w);
    R[6] = 2.f * (x * z - y * w);
    R[7] = 2.f * (y * z + x * w);
    R[8] = 1.f - 2.f * (x * x + y * y);
}

__global__ __launch_bounds__(TPB) void adl_fused_kernel(
    const float* __restrict__ poses_pred,
    const float* __restrict__ poses_target,
    const float* __restrict__ poses_weight,
    const float* __restrict__ points,
    const float* __restrict__ symmetry,
    float* __restrict__ out, int out_size, float inv_scale, int B)
{
    __shared__ ulonglong2 s_A[SEG];
    __shared__ ulonglong2 s_B[SEG];
    __shared__ float s_red[TPB / 32];
    __shared__ unsigned s_flag;

    const int i     = blockIdx.x;
    const int tid   = threadIdx.x;
    const int total = B * BLKB;
    const int b     = i % B;        // fine interleave of heavy/light blocks
    const int sub   = i / B;

    // ---- class selection (redundant per block; cheap) ----
    int  cls   = 0;
    bool valid = false;
    #pragma unroll
    for (int c = 0; c < NC; c++) {
        float w = poses_weight[b * 4 * NC + 4 * c];
        if (!valid && w > 0.f) { cls = c; valid = true; }
    }

    if (valid) {
        const float* qp = poses_pred   + b * 4 * NC + 4 * cls;
        const float* qg = poses_target + b * 4 * NC + 4 * cls;
        const bool   sym = symmetry[cls] > 0.f;
        const float* pts = points + (size_t)cls * NP * 3;
        float Rp[9], Rg[9];
        quat2rot(qp[0], qp[1], qp[2], qp[3], Rp);
        quat2rot(qg[0], qg[1], qg[2], qg[3], Rg);

        if (!sym) {
            if (sub == 0) {
                float acc = 0.f;
                for (int j = tid; j < NP; j += TPB) {
                    const float* p0 = pts + (size_t)j * 3;
                    float x0 = p0[0], y0 = p0[1], z0 = p0[2];
                    float gx = Rg[0]*x0 + Rg[1]*y0 + Rg[2]*z0;
                    float gy = Rg[3]*x0 + Rg[4]*y0 + Rg[5]*z0;
                    float gz = Rg[6]*x0 + Rg[7]*y0 + Rg[8]*z0;
                    float ax = Rp[0]*x0 + Rp[1]*y0 + Rp[2]*z0;
                    float ay = Rp[3]*x0 + Rp[4]*y0 + Rp[5]*z0;
                    float az = Rp[6]*x0 + Rp[7]*y0 + Rp[8]*z0;
                    float dx = ax - gx, dy = ay - gy, dz = az - gz;
                    float d = dx*dx + dy*dy + dz*dz;
                    acc += 0.5f * fmaxf(d - MARGIN, 0.f);
                }
                acc *= inv_scale;
                #pragma unroll
                for (int off = 16; off > 0; off >>= 1)
                    acc += __shfl_down_sync(0xFFFFFFFFu, acc, off);
                if ((tid & 31) == 0) s_red[tid >> 5] = acc;
                __syncthreads();
                if (tid == 0) g_bsum[b] = s_red[0] + s_red[1] + s_red[2] + s_red[3];
            }
        } else {
            const int pchunk = sub & (PCH - 1);
            const int qseg   = sub / PCH;

            // build this block's q-segment tile in shared (threads 0..SEG-1)
            if (tid < SEG) {
                const float* q0 = pts + (size_t)(qseg * SEG + tid) * 6;  // 2 points
                float x0 = q0[0], y0 = q0[1], z0 = q0[2];
                float x1 = q0[3], y1 = q0[4], z1 = q0[5];
                float gx0 = Rg[0]*x0 + Rg[1]*y0 + Rg[2]*z0;
                float gy0 = Rg[3]*x0 + Rg[4]*y0 + Rg[5]*z0;
                float gz0 = Rg[6]*x0 + Rg[7]*y0 + Rg[8]*z0;
                float gx1 = Rg[0]*x1 + Rg[1]*y1 + Rg[2]*z1;
                float gy1 = Rg[3]*x1 + Rg[4]*y1 + Rg[5]*z1;
                float gz1 = Rg[6]*x1 + Rg[7]*y1 + Rg[8]*z1;
                float n0 = gx0*gx0 + gy0*gy0 + gz0*gz0;
                float n1 = gx1*gx1 + gy1*gy1 + gz1*gz1;
                ulonglong2 A, Bv;
                A.x  = pack2(-2.f * gx0, -2.f * gx1);
                A.y  = pack2(-2.f * gy0, -2.f * gy1);
                Bv.x = pack2(-2.f * gz0, -2.f * gz1);
                Bv.y = pack2(n0, n1);
                s_A[tid] = A;
                s_B[tid] = Bv;
            }
            __syncthreads();

            // rotate this thread's PT points by predicted pose
            const int p_base = pchunk * (TPB * PT) + tid;
            ull ax[PT], ay[PT], az[PT];
            float nn[PT];
            #pragma unroll
            for (int u = 0; u < PT; u++) {
                const float* p0 = pts + (size_t)(p_base + u * TPB) * 3;
                float x0 = p0[0], y0 = p0[1], z0 = p0[2];
                float x = Rp[0]*x0 + Rp[1]*y0 + Rp[2]*z0;
                float y = Rp[3]*x0 + Rp[4]*y0 + Rp[5]*z0;
                float z = Rp[6]*x0 + Rp[7]*y0 + Rp[8]*z0;
                nn[u] = x*x + y*y + z*z;
                ax[u] = pack2(x, x);
                ay[u] = pack2(y, y);
                az[u] = pack2(z, z);
            }

            float mA[PT], mB[PT];
            #pragma unroll
            for (int u = 0; u < PT; u++) { mA[u] = 3.4e38f; mB[u] = 3.4e38f; }

            #pragma unroll 2
            for (int j = 0; j < SEG; j += 2) {
                ulonglong2 A0 = s_A[j + 0], B0 = s_B[j + 0];
                ulonglong2 A1 = s_A[j + 1], B1 = s_B[j + 1];
                #pragma unroll
                for (int u = 0; u < PT; u++) {
                    ull t0 = fma2(ax[u], A0.x, fma2(ay[u], A0.y, fma2(az[u], B0.x, B0.y)));
                    ull t1 = fma2(ax[u], A1.x, fma2(ay[u], A1.y, fma2(az[u], B1.x, B1.y)));
                    float l0, h0, l1, h1;
                    unpack2(t0, l0, h0);
                    unpack2(t1, l1, h1);
                    mA[u] = fminf(mA[u], fminf(l0, h0));
                    mB[u] = fminf(mB[u], fminf(l1, h1));
                }
            }

            #pragma unroll
            for (int u = 0; u < PT; u++) {
                // clamp commutes with min; key = FINF - bits(d) > 0, so max-key == min-d, empty=0
                float d = fmaxf(fminf(mA[u], mB[u]) + nn[u], 0.f);
                atomicMax(&g_pmin[b * NP + p_base + u * TPB], FINF_BITS - __float_as_int(d));
            }

            // per-batch finish: last of 16 blocks reduces + resets this batch's keys
            __syncthreads();
            if (tid == 0) {
                __threadfence();
                s_flag = (atomicInc(&g_bdone[b], (unsigned)BLKB - 1) == (unsigned)BLKB - 1);
            }
            __syncthreads();
            if (s_flag) {
                float vs = 0.f;
                #pragma unroll
                for (int k = tid; k < NP; k += TPB) {
                    int key = __ldcg(&g_pmin[b * NP + k]);
                    float d = __int_as_float(FINF_BITS - key);
                    vs += fmaxf(d - MARGIN, 0.f);
                    g_pmin[b * NP + k] = 0;   // reset for next launch / replay
                }
                vs *= 0.5f * inv_scale;
                #pragma unroll
                for (int off = 16; off > 0; off >>= 1)
                    vs += __shfl_down_sync(0xFFFFFFFFu, vs, off);
                if ((tid & 31) == 0) s_red[tid >> 5] = vs;
                __syncthreads();
                if (tid == 0) g_bsum[b] = s_red[0] + s_red[1] + s_red[2] + s_red[3];
            }
        }
    } else {
        if (sub == 0 && tid == 0) g_bsum[b] = 0.f;
    }

    // ---- global finish (self-resetting counter) ----
    if (tid == 0) {
        __threadfence();
        s_flag = (atomicInc(&g_done, (unsigned)total - 1) == (unsigned)total - 1);
    }
    __syncthreads();
    if (s_flag) {
        float v = 0.f;
        for (int k = tid; k < B; k += TPB)
            v += __ldcg(&g_bsum[k]);
        #pragma unroll
        for (int off = 16; off > 0; off >>= 1)
            v += __shfl_down_sync(0xFFFFFFFFu, v, off);
        if ((tid & 31) == 0) s_red[tid >> 5] = v;
        __syncthreads();
        if (tid == 0) {
            out[0] = s_red[0] + s_red[1] + s_red[2] + s_red[3];
            for (int k = 1; k < out_size; k++) out[k] = 0.f;
        }
    }
}

extern "C" void kernel_launch(void* const* d_in, const int* in_sizes, int n_in,
                              void* d_out, int out_size) {
    const float* poses_pred   = (const float*)d_in[0];
    const float* poses_target = (const float*)d_in[1];
    const float* poses_weight = (const float*)d_in[2];
    const float* points       = (const float*)d_in[3];
    const float* symmetry     = (const float*)d_in[4];
    float* out = (float*)d_out;

    const int B = in_sizes[0] / (4 * NC);
    const float inv_scale = 1.0f / ((float)B * (float)NP);

    adl_fused_kernel<<<B * BLKB, TPB>>>(
        poses_pred, poses_target, poses_weight, points, symmetry,
        out, out_size, inv_scale, B);
}